// round 15
// baseline (speedup 1.0000x reference)
#include <cuda_runtime.h>

#define NPART  524288
#define NMODE  8
#define NPSI   512
#define THREADS 512

typedef unsigned long long u64;

// Derived per-mode parameters: 32 floats per mode, all float4-aligned groups:
// [0..3]  = {ips, mps0, ias, nas}
// [4..7]  = {negnf, wt, nf, pad}
// [8..11] = d0[s0..s3]   (s0=(re,f0) s1=(re,f1) s2=(im,f0) s3=(im,f1))
// [12..15]= c1  [16..19]= q  [20..23]= b0  [24..27]= c4  [28..31]= C
__constant__ __align__(16) float c_par[NMODE * 32];

__device__ __forceinline__ u64 pk(float lo, float hi) {
    u64 r; asm("mov.b64 %0, {%1, %2};" : "=l"(r) : "f"(lo), "f"(hi)); return r;
}
__device__ __forceinline__ u64 pk2(float v) { return pk(v, v); }
__device__ __forceinline__ void upk(u64 v, float& lo, float& hi) {
    asm("mov.b64 {%0, %1}, %2;" : "=f"(lo), "=f"(hi) : "l"(v));
}
__device__ __forceinline__ u64 fma2(u64 a, u64 b, u64 c) {
    u64 d; asm("fma.rn.f32x2 %0, %1, %2, %3;" : "=l"(d) : "l"(a), "l"(b), "l"(c)); return d;
}
__device__ __forceinline__ float ex2f(float a) {
    float r; asm("ex2.approx.ftz.f32 %0, %1;" : "=f"(r) : "f"(a)); return r;
}
__device__ __forceinline__ float sinap(float a) {
    float r; asm("sin.approx.ftz.f32 %0, %1;" : "=f"(r) : "f"(a)); return r;
}
__device__ __forceinline__ float cosap(float a) {
    float r; asm("cos.approx.ftz.f32 %0, %1;" : "=f"(r) : "f"(a)); return r;
}

// Writes derived params straight into the constant bank's backing store.
// Coherent for the NEXT kernel launch (constant cache is cold per launch).
__global__ void eik_prep(const float* __restrict__ tsc,
                         const float* __restrict__ gh_re,
                         const float* __restrict__ gh_im,
                         const float* __restrict__ psi0,
                         const float* __restrict__ psi_scale,
                         const float* __restrict__ alpha_scale,
                         const float* __restrict__ omega,
                         const int*   __restrict__ nmode,
                         float* __restrict__ cbak)
{
    const int m = threadIdx.x;
    if (m < NMODE) {
        const float t   = tsc[0];
        const float ips = 1.0f / psi_scale[m];
        const float ass = alpha_scale[m];
        const float nf  = (float)nmode[m];
        float* P = &cbak[m * 32];
        P[0] = ips;
        P[1] = -psi0[m] * ips;
        P[2] = 1.0f / ass;
        P[3] = nf * ass;          // nas
        P[4] = -nf;
        P[5] = omega[m] * t;
        P[6] = nf;
        P[7] = 0.0f;
        #pragma unroll
        for (int s = 0; s < 4; s++) {
            const float* gh = (s < 2) ? gh_re : gh_im;
            const int f = s & 1;
            const float c0 = gh[m*12 + 0*2 + f];
            const float c1 = gh[m*12 + 1*2 + f];
            const float c2 = gh[m*12 + 2*2 + f];
            const float c3 = gh[m*12 + 3*2 + f];
            const float c4 = gh[m*12 + 4*2 + f];
            const float c5 = gh[m*12 + 5*2 + f];
            P[8  + s] = c0 - 2.0f*c3 - 2.0f*c5;  // d0
            P[12 + s] = c1;
            P[16 + s] = 4.0f*c3;                 // q
            P[20 + s] = c2;                      // b0
            P[24 + s] = c4;
            P[28 + s] = 4.0f*c5;                 // C
        }
    }
    __threadfence();
    cudaTriggerProgrammaticLaunchCompletion();
}

__global__ __launch_bounds__(THREADS)
void eik_main(const float* __restrict__ r,
              const float* __restrict__ varphi,
              const float* __restrict__ z,
              const float* __restrict__ psi,
              const float* __restrict__ a0_tab,     // [NPSI][NMODE]
              const float* __restrict__ iota_tab,   // [NPSI]
              float2* __restrict__ out)
{
    // row: [0]=a0 modes0-3, [1]=a0 modes4-7, [2].x=iota (rest pad)
    __shared__ float4 sh_tab[NPSI][3];

    const int tid = threadIdx.x;

    const float4* a0v = (const float4*)a0_tab;
    for (int idx = tid; idx < NPSI * 2; idx += THREADS)
        sh_tab[idx >> 1][idx & 1] = a0v[idx];
    for (int idx = tid; idx < NPSI; idx += THREADS)
        sh_tab[idx][2].x = iota_tab[idx];
    __syncthreads();

    const int gid = blockIdx.x * THREADS + tid;

    const float TWO_PI_F = 6.28318530717958647692f;
    const float DXf = (float)(1.0 / 511.0);
    const float INV2PI  = 0.15915494309189535f;
    const float MAGIC   = 12582912.0f;            // 1.5 * 2^23
    const float PI2_HI  = 6.28318548202514648f;
    const float NHL2E   = -0.72134752044448170368f;  // -0.5*log2(e)

    const u64 INV2PI2 = pk2(INV2PI);
    const u64 MAGIC2  = pk2(MAGIC);
    const u64 NMAGIC2 = pk2(-MAGIC);
    const u64 ONE2    = pk2(1.0f);
    const u64 NPI2HI2 = pk2(-PI2_HI);

    const float rr = r[gid];
    const float zz = z[gid];
    const float ps = psi[gid];
    const float vp = varphi[gid];

    const float theta = atan2f(zz, rr - 1.7f);

    const float s = ps / DXf;
    int i = (int)floorf(s);
    i = (i < 1) ? 1 : ((i > NPSI - 3) ? (NPSI - 3) : i);
    const float ttv = s - (float)i;
    const float t2 = ttv * ttv;
    const float t3 = t2 * ttv;
    const float wm1 = 0.5f * (-t3 + 2.0f * t2 - ttv);
    const float w0  = 0.5f * (3.0f * t3 - 5.0f * t2 + 2.0f);
    const float w1  = 0.5f * (-3.0f * t3 + 4.0f * t2 + ttv);
    const float w2  = 0.5f * (t3 - t2);

    const float io = wm1 * sh_tab[i-1][2].x + w0 * sh_tab[i][2].x
                   + w1  * sh_tab[i+1][2].x + w2 * sh_tab[i+2][2].x;

    const ulonglong2 R0v = *(const ulonglong2*)&sh_tab[i-1][0];
    const ulonglong2 R0w = *(const ulonglong2*)&sh_tab[i-1][1];
    const ulonglong2 R1v = *(const ulonglong2*)&sh_tab[i  ][0];
    const ulonglong2 R1w = *(const ulonglong2*)&sh_tab[i  ][1];
    const ulonglong2 R2v = *(const ulonglong2*)&sh_tab[i+1][0];
    const ulonglong2 R2w = *(const ulonglong2*)&sh_tab[i+1][1];
    const ulonglong2 R3v = *(const ulonglong2*)&sh_tab[i+2][0];
    const ulonglong2 R3w = *(const ulonglong2*)&sh_tab[i+2][1];
    const u64 wm1p = pk2(wm1), w0p = pk2(w0), w1p = pk2(w1), w2p = pk2(w2);
    const u64 zz2 = pk(0.0f, 0.0f);
    u64 am01 = fma2(w2p, R3v.x, fma2(w1p, R2v.x, fma2(w0p, R1v.x, fma2(wm1p, R0v.x, zz2))));
    u64 am23 = fma2(w2p, R3v.y, fma2(w1p, R2v.y, fma2(w0p, R1v.y, fma2(wm1p, R0v.y, zz2))));
    u64 am45 = fma2(w2p, R3w.x, fma2(w1p, R2w.x, fma2(w0p, R1w.x, fma2(wm1p, R0w.x, zz2))));
    u64 am67 = fma2(w2p, R3w.y, fma2(w1p, R2w.y, fma2(w0p, R1w.y, fma2(wm1p, R0w.y, zz2))));

    const float al1 = io * theta;
    const float dal = io * TWO_PI_F;

    // Params become visible only after the prep kernel is done.
    cudaGridDependencySynchronize();

    u64 acc = pk(0.0f, 0.0f);

    #pragma unroll
    for (int m = 0; m < NMODE; m++) {
        const float* P = &c_par[m * 32];
        const float4 F0 = *(const float4*)&P[0];   // ips, mps0, ias, nas
        const float4 F1 = *(const float4*)&P[4];   // negnf, wt, nf, -
        const ulonglong2 d0  = *(const ulonglong2*)&P[8];    // (re, im)
        const ulonglong2 c1v = *(const ulonglong2*)&P[12];
        const ulonglong2 qv  = *(const ulonglong2*)&P[16];
        const ulonglong2 b0v = *(const ulonglong2*)&P[20];
        const ulonglong2 c4v = *(const ulonglong2*)&P[24];
        const ulonglong2 Cv  = *(const ulonglong2*)&P[28];

        float a0lo, a0hi, a0m;
        if (m < 2)      upk(am01, a0lo, a0hi);
        else if (m < 4) upk(am23, a0lo, a0hi);
        else if (m < 6) upk(am45, a0lo, a0hi);
        else            upk(am67, a0lo, a0hi);
        a0m = (m & 1) ? a0hi : a0lo;

        const float x  = fmaf(ps, F0.x, F0.y);
        const float x2 = x * x;
        const float ph0 = fmaf(F1.x, vp, F1.y);  // wt - n*vp
        const float x2h = x2 * NHL2E;

        const u64 xp  = pk2(x);
        const u64 x2p = pk2(x2);
        const u64 Aa_re = fma2(qv.x, x2p, fma2(c1v.x, xp, d0.x));
        const u64 Aa_im = fma2(qv.y, x2p, fma2(c1v.y, xp, d0.y));
        const u64 Bb_re = fma2(c4v.x, xp, b0v.x);
        const u64 Bb_im = fma2(c4v.y, xp, b0v.y);

        const float y1  = (al1 - a0m) * F0.z;
        const float dlt = dal * F0.z;
        const float Dph = F1.z * dal;          // n * iota * 2pi
        const float ph1 = fmaf(F0.w, y1, ph0);

        // Only 2 of the 3 alpha branches ever contribute (dlt >= ~7.8, the
        // far-side branch has g <= e^-30). Branch A = y1; branch B =
        // y1 - sgn*dlt with phase phB = ph1 - sgn*Dph.
        const float sgn1 = copysignf(1.0f, y1);
        const float yB   = fmaf(-sgn1, dlt, y1);
        const float phB  = fmaf(-sgn1, Dph, ph1);

        // packed range reduction of (ph1, phB) into [-pi, pi]
        const u64 php = pk(ph1, phB);
        const u64 tq  = fma2(php, INV2PI2, MAGIC2);
        const u64 kq  = fma2(tq, ONE2, NMAGIC2);
        const u64 phr2 = fma2(kq, NPI2HI2, php);
        float phrA, phrB; upk(phr2, phrA, phrB);

        // 4 independent MUFU ops
        const float s1 = sinap(phrA);
        const float c1 = cosap(phrA);
        const float sB = sinap(phrB);
        const float cB = cosap(phrB);

        #pragma unroll
        for (int k = 0; k < 2; k++) {
            const float yk = (k == 0) ? y1 : yB;
            const float ck = (k == 0) ? c1 : cB;
            const float sk = (k == 0) ? s1 : sB;

            const float yh = yk * NHL2E;
            const float ek = ex2f(fmaf(yh, yk, x2h));

            const u64 yp = pk2(yk);
            const u64 pre = fma2(yp, fma2(Cv.x, yp, Bb_re), Aa_re);
            const u64 pim = fma2(yp, fma2(Cv.y, yp, Bb_im), Aa_im);

            const float gc = ek * ck;
            const float gs = -ek * sk;
            acc = fma2(pk2(gc), pre, acc);
            acc = fma2(pk2(gs), pim, acc);
        }
    }

    float o0, o1;
    upk(acc, o0, o1);
    out[gid] = make_float2(o0, o1);
}

extern "C" void kernel_launch(void* const* d_in, const int* in_sizes, int n_in,
                              void* d_out, int out_size)
{
    (void)in_sizes; (void)n_in; (void)out_size;

    void* c_addr = nullptr;
    cudaGetSymbolAddress(&c_addr, c_par);

    eik_prep<<<1, 32>>>(
        (const float*)d_in[0],   // t
        (const float*)d_in[5],   // gh_re
        (const float*)d_in[6],   // gh_im
        (const float*)d_in[9],   // psi0
        (const float*)d_in[10],  // psi_scale
        (const float*)d_in[11],  // alpha_scale
        (const float*)d_in[12],  // omega
        (const int*)  d_in[13],  // n
        (float*)c_addr);

    // Programmatic dependent launch: main starts while prep runs; it gates
    // its constant reads with cudaGridDependencySynchronize().
    cudaLaunchConfig_t cfg = {};
    cfg.gridDim  = dim3(NPART / THREADS, 1, 1);
    cfg.blockDim = dim3(THREADS, 1, 1);
    cfg.dynamicSmemBytes = 0;
    cfg.stream = 0;
    cudaLaunchAttribute attrs[1];
    attrs[0].id = cudaLaunchAttributeProgrammaticStreamSerialization;
    attrs[0].val.programmaticStreamSerializationAllowed = 1;
    cfg.attrs = attrs;
    cfg.numAttrs = 1;

    cudaLaunchKernelEx(&cfg, eik_main,
        (const float*)d_in[1],   // r
        (const float*)d_in[2],   // varphi
        (const float*)d_in[3],   // z
        (const float*)d_in[4],   // psi
        (const float*)d_in[7],   // alpha0_table
        (const float*)d_in[8],   // iota_table
        (float2*)d_out);
}

// round 16
// speedup vs baseline: 1.0137x; 1.0137x over previous
#include <cuda_runtime.h>

#define NPART  524288
#define NMODE  8
#define NPSI   512
#define THREADS 512

typedef unsigned long long u64;

// Derived per-mode parameters: 32 floats per mode, all float4-aligned groups:
// [0..3]  = {ips, mps0, ias, nas}
// [4..7]  = {negnf, wt, nf, pad}
// [8..11] = d0[s0..s3]   (s0=(re,f0) s1=(re,f1) s2=(im,f0) s3=(im,f1))
// [12..15]= c1  [16..19]= q  [20..23]= b0  [24..27]= c4  [28..31]= C
__constant__ __align__(16) float c_par[NMODE * 32];

__device__ __forceinline__ u64 pk(float lo, float hi) {
    u64 r; asm("mov.b64 %0, {%1, %2};" : "=l"(r) : "f"(lo), "f"(hi)); return r;
}
__device__ __forceinline__ u64 pk2(float v) { return pk(v, v); }
__device__ __forceinline__ void upk(u64 v, float& lo, float& hi) {
    asm("mov.b64 {%0, %1}, %2;" : "=f"(lo), "=f"(hi) : "l"(v));
}
__device__ __forceinline__ u64 fma2(u64 a, u64 b, u64 c) {
    u64 d; asm("fma.rn.f32x2 %0, %1, %2, %3;" : "=l"(d) : "l"(a), "l"(b), "l"(c)); return d;
}
__device__ __forceinline__ float ex2f(float a) {
    float r; asm("ex2.approx.ftz.f32 %0, %1;" : "=f"(r) : "f"(a)); return r;
}
__device__ __forceinline__ float sinap(float a) {
    float r; asm("sin.approx.ftz.f32 %0, %1;" : "=f"(r) : "f"(a)); return r;
}
__device__ __forceinline__ float cosap(float a) {
    float r; asm("cos.approx.ftz.f32 %0, %1;" : "=f"(r) : "f"(a)); return r;
}

// Writes derived params straight into the constant bank's backing store.
// Coherent for the NEXT kernel launch (constant cache is cold per launch).
__global__ void eik_prep(const float* __restrict__ tsc,
                         const float* __restrict__ gh_re,
                         const float* __restrict__ gh_im,
                         const float* __restrict__ psi0,
                         const float* __restrict__ psi_scale,
                         const float* __restrict__ alpha_scale,
                         const float* __restrict__ omega,
                         const int*   __restrict__ nmode,
                         float* __restrict__ cbak)
{
    const int m = threadIdx.x;
    if (m < NMODE) {
        const float t   = tsc[0];
        const float ips = 1.0f / psi_scale[m];
        const float ass = alpha_scale[m];
        const float nf  = (float)nmode[m];
        float* P = &cbak[m * 32];
        P[0] = ips;
        P[1] = -psi0[m] * ips;
        P[2] = 1.0f / ass;
        P[3] = nf * ass;          // nas
        P[4] = -nf;
        P[5] = omega[m] * t;
        P[6] = nf;
        P[7] = 0.0f;
        #pragma unroll
        for (int s = 0; s < 4; s++) {
            const float* gh = (s < 2) ? gh_re : gh_im;
            const int f = s & 1;
            const float c0 = gh[m*12 + 0*2 + f];
            const float c1 = gh[m*12 + 1*2 + f];
            const float c2 = gh[m*12 + 2*2 + f];
            const float c3 = gh[m*12 + 3*2 + f];
            const float c4 = gh[m*12 + 4*2 + f];
            const float c5 = gh[m*12 + 5*2 + f];
            P[8  + s] = c0 - 2.0f*c3 - 2.0f*c5;  // d0
            P[12 + s] = c1;
            P[16 + s] = 4.0f*c3;                 // q
            P[20 + s] = c2;                      // b0
            P[24 + s] = c4;
            P[28 + s] = 4.0f*c5;                 // C
        }
    }
    __threadfence();
    cudaTriggerProgrammaticLaunchCompletion();
}

__global__ __launch_bounds__(THREADS)
void eik_main(const float* __restrict__ r,
              const float* __restrict__ varphi,
              const float* __restrict__ z,
              const float* __restrict__ psi,
              const float* __restrict__ a0_tab,     // [NPSI][NMODE]
              const float* __restrict__ iota_tab,   // [NPSI]
              float2* __restrict__ out)
{
    const int tid = threadIdx.x;
    const int gid = blockIdx.x * THREADS + tid;

    const float TWO_PI_F = 6.28318530717958647692f;
    const float DXf = (float)(1.0 / 511.0);
    const float INV2PI  = 0.15915494309189535f;
    const float MAGIC   = 12582912.0f;            // 1.5 * 2^23
    const float PI2_HI  = 6.28318548202514648f;
    const float NHL2E   = -0.72134752044448170368f;  // -0.5*log2(e)

    const u64 INV2PI2 = pk2(INV2PI);
    const u64 MAGIC2  = pk2(MAGIC);
    const u64 NMAGIC2 = pk2(-MAGIC);
    const u64 ONE2    = pk2(1.0f);
    const u64 NPI2HI2 = pk2(-PI2_HI);

    const float rr = r[gid];
    const float zz = z[gid];
    const float ps = psi[gid];
    const float vp = varphi[gid];

    const float theta = atan2f(zz, rr - 1.7f);

    const float s = ps / DXf;
    int i = (int)floorf(s);
    i = (i < 1) ? 1 : ((i > NPSI - 3) ? (NPSI - 3) : i);
    const float ttv = s - (float)i;
    const float t2 = ttv * ttv;
    const float t3 = t2 * ttv;
    const float wm1 = 0.5f * (-t3 + 2.0f * t2 - ttv);
    const float w0  = 0.5f * (3.0f * t3 - 5.0f * t2 + 2.0f);
    const float w1  = 0.5f * (-3.0f * t3 + 4.0f * t2 + ttv);
    const float w2  = 0.5f * (t3 - t2);

    // Direct L1 gathers — tables (18 KB total) stay hot in L1D across CTAs
    // on the same SM within the launch; no smem staging, no barrier.
    const float io = wm1 * iota_tab[i-1] + w0 * iota_tab[i]
                   + w1  * iota_tab[i+1] + w2 * iota_tab[i+2];

    const ulonglong2* a0v = (const ulonglong2*)a0_tab;   // 2 x u64 per row of 8
    const ulonglong2 R0v = a0v[(i-1)*2 + 0];
    const ulonglong2 R0w = a0v[(i-1)*2 + 1];
    const ulonglong2 R1v = a0v[(i  )*2 + 0];
    const ulonglong2 R1w = a0v[(i  )*2 + 1];
    const ulonglong2 R2v = a0v[(i+1)*2 + 0];
    const ulonglong2 R2w = a0v[(i+1)*2 + 1];
    const ulonglong2 R3v = a0v[(i+2)*2 + 0];
    const ulonglong2 R3w = a0v[(i+2)*2 + 1];
    const u64 wm1p = pk2(wm1), w0p = pk2(w0), w1p = pk2(w1), w2p = pk2(w2);
    const u64 zz2 = pk(0.0f, 0.0f);
    u64 am01 = fma2(w2p, R3v.x, fma2(w1p, R2v.x, fma2(w0p, R1v.x, fma2(wm1p, R0v.x, zz2))));
    u64 am23 = fma2(w2p, R3v.y, fma2(w1p, R2v.y, fma2(w0p, R1v.y, fma2(wm1p, R0v.y, zz2))));
    u64 am45 = fma2(w2p, R3w.x, fma2(w1p, R2w.x, fma2(w0p, R1w.x, fma2(wm1p, R0w.x, zz2))));
    u64 am67 = fma2(w2p, R3w.y, fma2(w1p, R2w.y, fma2(w0p, R1w.y, fma2(wm1p, R0w.y, zz2))));

    const float al1 = io * theta;
    const float dal = io * TWO_PI_F;

    // Params become visible only after the prep kernel is done.
    cudaGridDependencySynchronize();

    u64 acc = pk(0.0f, 0.0f);

    #pragma unroll
    for (int m = 0; m < NMODE; m++) {
        const float* P = &c_par[m * 32];
        const float4 F0 = *(const float4*)&P[0];   // ips, mps0, ias, nas
        const float4 F1 = *(const float4*)&P[4];   // negnf, wt, nf, -
        const ulonglong2 d0  = *(const ulonglong2*)&P[8];    // (re, im)
        const ulonglong2 c1v = *(const ulonglong2*)&P[12];
        const ulonglong2 qv  = *(const ulonglong2*)&P[16];
        const ulonglong2 b0v = *(const ulonglong2*)&P[20];
        const ulonglong2 c4v = *(const ulonglong2*)&P[24];
        const ulonglong2 Cv  = *(const ulonglong2*)&P[28];

        float a0lo, a0hi, a0m;
        if (m < 2)      upk(am01, a0lo, a0hi);
        else if (m < 4) upk(am23, a0lo, a0hi);
        else if (m < 6) upk(am45, a0lo, a0hi);
        else            upk(am67, a0lo, a0hi);
        a0m = (m & 1) ? a0hi : a0lo;

        const float x  = fmaf(ps, F0.x, F0.y);
        const float x2 = x * x;
        const float ph0 = fmaf(F1.x, vp, F1.y);  // wt - n*vp
        const float x2h = x2 * NHL2E;

        const u64 xp  = pk2(x);
        const u64 x2p = pk2(x2);
        const u64 Aa_re = fma2(qv.x, x2p, fma2(c1v.x, xp, d0.x));
        const u64 Aa_im = fma2(qv.y, x2p, fma2(c1v.y, xp, d0.y));
        const u64 Bb_re = fma2(c4v.x, xp, b0v.x);
        const u64 Bb_im = fma2(c4v.y, xp, b0v.y);

        const float y1  = (al1 - a0m) * F0.z;
        const float dlt = dal * F0.z;
        const float Dph = F1.z * dal;          // n * iota * 2pi
        const float ph1 = fmaf(F0.w, y1, ph0);

        // Only 2 of the 3 alpha branches ever contribute (dlt >= ~7.8, the
        // far-side branch has g <= e^-30). Branch A = y1; branch B =
        // y1 - copysign(dlt, y1), phase phB = ph1 - copysign(Dph, y1).
        const float dltS = copysignf(dlt, y1);
        const float DphS = copysignf(Dph, y1);
        const float yB   = y1 - dltS;
        const float phB  = ph1 - DphS;

        // packed range reduction of (ph1, phB) into [-pi, pi]
        const u64 php = pk(ph1, phB);
        const u64 tq  = fma2(php, INV2PI2, MAGIC2);
        const u64 kq  = fma2(tq, ONE2, NMAGIC2);
        const u64 phr2 = fma2(kq, NPI2HI2, php);
        float phrA, phrB; upk(phr2, phrA, phrB);

        // 4 independent MUFU ops
        const float s1 = sinap(phrA);
        const float c1 = cosap(phrA);
        const float sB = sinap(phrB);
        const float cB = cosap(phrB);

        #pragma unroll
        for (int k = 0; k < 2; k++) {
            const float yk = (k == 0) ? y1 : yB;
            const float ck = (k == 0) ? c1 : cB;
            const float sk = (k == 0) ? s1 : sB;

            const float yh = yk * NHL2E;
            const float ek = ex2f(fmaf(yh, yk, x2h));

            const u64 yp = pk2(yk);
            const u64 pre = fma2(yp, fma2(Cv.x, yp, Bb_re), Aa_re);
            const u64 pim = fma2(yp, fma2(Cv.y, yp, Bb_im), Aa_im);

            const float gc = ek * ck;
            const float gs = -ek * sk;
            acc = fma2(pk2(gc), pre, acc);
            acc = fma2(pk2(gs), pim, acc);
        }
    }

    float o0, o1;
    upk(acc, o0, o1);
    out[gid] = make_float2(o0, o1);
}

extern "C" void kernel_launch(void* const* d_in, const int* in_sizes, int n_in,
                              void* d_out, int out_size)
{
    (void)in_sizes; (void)n_in; (void)out_size;

    void* c_addr = nullptr;
    cudaGetSymbolAddress(&c_addr, c_par);

    eik_prep<<<1, 32>>>(
        (const float*)d_in[0],   // t
        (const float*)d_in[5],   // gh_re
        (const float*)d_in[6],   // gh_im
        (const float*)d_in[9],   // psi0
        (const float*)d_in[10],  // psi_scale
        (const float*)d_in[11],  // alpha_scale
        (const float*)d_in[12],  // omega
        (const int*)  d_in[13],  // n
        (float*)c_addr);

    // Programmatic dependent launch: main starts while prep runs; it gates
    // its constant reads with cudaGridDependencySynchronize().
    cudaLaunchConfig_t cfg = {};
    cfg.gridDim  = dim3(NPART / THREADS, 1, 1);
    cfg.blockDim = dim3(THREADS, 1, 1);
    cfg.dynamicSmemBytes = 0;
    cfg.stream = 0;
    cudaLaunchAttribute attrs[1];
    attrs[0].id = cudaLaunchAttributeProgrammaticStreamSerialization;
    attrs[0].val.programmaticStreamSerializationAllowed = 1;
    cfg.attrs = attrs;
    cfg.numAttrs = 1;

    cudaLaunchKernelEx(&cfg, eik_main,
        (const float*)d_in[1],   // r
        (const float*)d_in[2],   // varphi
        (const float*)d_in[3],   // z
        (const float*)d_in[4],   // psi
        (const float*)d_in[7],   // alpha0_table
        (const float*)d_in[8],   // iota_table
        (float2*)d_out);
}